// round 16
// baseline (speedup 1.0000x reference)
#include <cuda_runtime.h>
#include <math.h>
#include <float.h>
#include <stdint.h>

// Shapes (fixed): z_e [32,64,64,64] f32, emb [512,64] f32.
#define N_TOK    131072
#define HW       4096
#define OFF_SCAL 8388608
#define OFF_IDX  8388613

// Scratch (static device globals: allocation-free).
__device__ float        g_bnorm[512];
__device__ unsigned int g_counts[512];
__device__ double       g_dsum;
__device__ int          g_done;

typedef unsigned long long ull;

// ---- packed f32x2 helpers (Blackwell packed fp32 pipe) ----
__device__ __forceinline__ ull fma2(ull a, ull b, ull c) {
    ull d;
    asm("fma.rn.f32x2 %0, %1, %2, %3;" : "=l"(d) : "l"(a), "l"(b), "l"(c));
    return d;
}
__device__ __forceinline__ ull add2(ull a, ull b) {
    ull d;
    asm("add.rn.f32x2 %0, %1, %2;" : "=l"(d) : "l"(a), "l"(b));
    return d;
}
__device__ __forceinline__ ull pack2(float lo, float hi) {
    ull d;
    asm("mov.b64 %0, {%1, %2};" : "=l"(d) : "f"(lo), "f"(hi));
    return d;
}
__device__ __forceinline__ float lanesum(ull s) {
    float lo, hi;
    asm("mov.b64 {%0, %1}, %2;" : "=f"(lo), "=f"(hi) : "l"(s));
    return lo + hi;
}

// ---- prep: code norms + zero accumulators ----
__global__ void vq_prep(const float* __restrict__ emb) {
    int k = blockIdx.x * 256 + threadIdx.x;     // 0..511
    const float* e = emb + k * 64;
    float s = 0.f;
#pragma unroll
    for (int d = 0; d < 64; ++d) s = fmaf(e[d], e[d], s);
    g_bnorm[k]  = s;
    g_counts[k] = 0u;
    if (k == 0) { g_dsum = 0.0; g_done = 0; }
}

// ---- main: persistent CTAs; per tile: argmin (k-loop unrolled x2 codes for ILP)
//      + fused z_q scatter; last CTA runs the scalar finalize in-kernel. ----
// smem: s_emb f32[32768] | s_bn f32[512] | s_hist u32[512] | s_md f32[512] | s_mi i32[512]
#define SM_FLOATS 34816
#define SM_BYTES  (SM_FLOATS * 4)     // 139264

__global__ __launch_bounds__(256, 1)
void vq_main(const float* __restrict__ z_e, const float* __restrict__ emb,
             float* __restrict__ out) {
    extern __shared__ __align__(16) float sm[];
    float*        s_emb  = sm;                          // 32768 f32 (raw emb rows)
    float*        s_bn   = sm + 32768;                  // 512
    unsigned int* s_hist = (unsigned int*)(sm + 33280); // 512
    float*        s_md   = sm + 33792;                  // 512
    int*          s_mi   = (int*)(sm + 34304);          // 512
    const int tid = threadIdx.x;

    for (int i = tid; i < 8192; i += 256)
        ((float4*)s_emb)[i] = ((const float4*)emb)[i];
    for (int i = tid; i < 512; i += 256) {
        s_bn[i]   = g_bnorm[i];
        s_hist[i] = 0u;
    }
    __syncthreads();

    const int quad  = tid >> 6;          // code quarter: codes [quad*128, +128)
    const int tp    = tid & 63;          // token slot
    const int kbase = quad * 128;

    for (int tile = (int)blockIdx.x; tile < 1024; tile += 148) {
        const int n0   = tile * 128;
        const int b    = n0 >> 12;
        const int hw0  = n0 & (HW - 1);
        const float* zp0 = z_e + ((size_t)b << 18) + hw0 + tp;
        const float* zp1 = zp0 + 64;

        // load both tokens, pack consecutive-d pairs, compute ||z||^2
        ull z0[32], z1[32];
        float a00 = 0.f, a01 = 0.f, a10 = 0.f, a11 = 0.f;
#pragma unroll
        for (int j = 0; j < 32; j += 2) {
            float u0 = zp0[(size_t)(2 * j + 0) << 12];
            float u1 = zp0[(size_t)(2 * j + 1) << 12];
            float u2 = zp0[(size_t)(2 * j + 2) << 12];
            float u3 = zp0[(size_t)(2 * j + 3) << 12];
            float v0 = zp1[(size_t)(2 * j + 0) << 12];
            float v1 = zp1[(size_t)(2 * j + 1) << 12];
            float v2 = zp1[(size_t)(2 * j + 2) << 12];
            float v3 = zp1[(size_t)(2 * j + 3) << 12];
            a00 = fmaf(u0, u0, a00); a00 = fmaf(u1, u1, a00);
            a01 = fmaf(u2, u2, a01); a01 = fmaf(u3, u3, a01);
            a10 = fmaf(v0, v0, a10); a10 = fmaf(v1, v1, a10);
            a11 = fmaf(v2, v2, a11); a11 = fmaf(v3, v3, a11);
            z0[j]     = pack2(u0, u1);
            z0[j + 1] = pack2(u2, u3);
            z1[j]     = pack2(v0, v1);
            z1[j + 1] = pack2(v2, v3);
        }
        const float A0 = a00 + a01;
        const float A1 = a10 + a11;

        float dmin0 = FLT_MAX, dmin1 = FLT_MAX;
        int   imin0 = 0,       imin1 = 0;
#pragma unroll 1
        for (int k = kbase; k < kbase + 128; k += 2) {
            const ulonglong2* rowA = (const ulonglong2*)(s_emb + (k << 6));
            const ulonglong2* rowB = rowA + 16;   // next code row (+64 floats = +16 u64x2)
            ull c00 = 0ull, c01 = 0ull, c10 = 0ull, c11 = 0ull;   // code k
            ull e00 = 0ull, e01 = 0ull, e10 = 0ull, e11 = 0ull;   // code k+1
#pragma unroll
            for (int j = 0; j < 16; j += 2) {
                ulonglong2 qa0 = rowA[j];
                ulonglong2 qa1 = rowA[j + 1];
                ulonglong2 qb0 = rowB[j];
                ulonglong2 qb1 = rowB[j + 1];
                c00 = fma2(z0[2 * j + 0], qa0.x, c00);
                c10 = fma2(z1[2 * j + 0], qa0.x, c10);
                e00 = fma2(z0[2 * j + 0], qb0.x, e00);
                e10 = fma2(z1[2 * j + 0], qb0.x, e10);
                c01 = fma2(z0[2 * j + 1], qa0.y, c01);
                c11 = fma2(z1[2 * j + 1], qa0.y, c11);
                e01 = fma2(z0[2 * j + 1], qb0.y, e01);
                e11 = fma2(z1[2 * j + 1], qb0.y, e11);
                c00 = fma2(z0[2 * j + 2], qa1.x, c00);
                c10 = fma2(z1[2 * j + 2], qa1.x, c10);
                e00 = fma2(z0[2 * j + 2], qb1.x, e00);
                e10 = fma2(z1[2 * j + 2], qb1.x, e10);
                c01 = fma2(z0[2 * j + 3], qa1.y, c01);
                c11 = fma2(z1[2 * j + 3], qa1.y, c11);
                e01 = fma2(z0[2 * j + 3], qb1.y, e01);
                e11 = fma2(z1[2 * j + 3], qb1.y, e11);
            }
            // epilogue code k (numerics identical to the proven single-code loop)
            {
                float bnk  = s_bn[k];
                float dot0 = lanesum(add2(c00, c01));
                float dot1 = lanesum(add2(c10, c11));
                float d0 = fmaf(dot0, -2.f, A0 + bnk);
                float d1 = fmaf(dot1, -2.f, A1 + bnk);
                if (d0 < dmin0) { dmin0 = d0; imin0 = k; }
                if (d1 < dmin1) { dmin1 = d1; imin1 = k; }
            }
            // epilogue code k+1 (ascending order: strict < keeps lowest index)
            {
                float bnk  = s_bn[k + 1];
                float dot0 = lanesum(add2(e00, e01));
                float dot1 = lanesum(add2(e10, e11));
                float d0 = fmaf(dot0, -2.f, A0 + bnk);
                float d1 = fmaf(dot1, -2.f, A1 + bnk);
                if (d0 < dmin0) { dmin0 = d0; imin0 = k + 1; }
                if (d1 < dmin1) { dmin1 = d1; imin1 = k + 1; }
            }
        }

        // publish per-quarter candidates
        s_md[quad * 128 + tp]      = dmin0;
        s_mi[quad * 128 + tp]      = imin0;
        s_md[quad * 128 + tp + 64] = dmin1;
        s_mi[quad * 128 + tp + 64] = imin1;
        __syncthreads();

        // merge across quarters (ascending quad = ascending code: strict < keeps
        // the lowest index on exact ties, matching the reference argmin)
        if (tid < 128) {
            float d = s_md[tid];
            int   i = s_mi[tid];
#pragma unroll
            for (int q = 1; q < 4; ++q) {
                float dq = s_md[q * 128 + tid];
                int   iq = s_mi[q * 128 + tid];
                if (dq < d) { d = dq; i = iq; }
            }
            int n = n0 + tid;
            out[OFF_IDX + n] = (float)i;
            s_mi[tid]        = i;            // final index for the scatter phase
            atomicAdd(&s_hist[i], 1u);
            float v = d;
#pragma unroll
            for (int o = 16; o; o >>= 1) v += __shfl_xor_sync(0xffffffffu, v, o);
            if ((tid & 31) == 0) atomicAdd(&g_dsum, (double)v);
        }
        __syncthreads();

        // fused z_q scatter: 512 items (32 token-groups x 16 d4), 2 per thread.
#pragma unroll
        for (int r = 0; r < 2; ++r) {
            int it = r * 256 + tid;
            int d4 = it >> 5;                 // 0..15 (uniform across a warp)
            int t4 = (it & 31) << 2;          // token group base 0..124
            const int4 ix = *(const int4*)(s_mi + t4);
            float4 e0 = *(const float4*)(emb + ix.x * 64 + d4 * 4);
            float4 e1 = *(const float4*)(emb + ix.y * 64 + d4 * 4);
            float4 e2 = *(const float4*)(emb + ix.z * 64 + d4 * 4);
            float4 e3 = *(const float4*)(emb + ix.w * 64 + d4 * 4);
            int base = (b << 18) + (d4 << 14) + hw0 + t4;
            *(float4*)(out + base         ) = make_float4(e0.x, e1.x, e2.x, e3.x);
            *(float4*)(out + base +  4096 ) = make_float4(e0.y, e1.y, e2.y, e3.y);
            *(float4*)(out + base +  8192 ) = make_float4(e0.z, e1.z, e2.z, e3.z);
            *(float4*)(out + base + 12288 ) = make_float4(e0.w, e1.w, e2.w, e3.w);
        }
        __syncthreads();   // protect s_md/s_mi/s_hist for the next tile
    }

    // flush per-CTA histogram once
    for (int i = tid; i < 512; i += 256) {
        unsigned int c = s_hist[i];
        if (c) atomicAdd(&g_counts[i], c);
    }
    __threadfence();
    __syncthreads();

    // ticket: the last CTA to finish runs the scalar finalize in-kernel
    if (tid == 0) s_hist[0] = (atomicAdd(&g_done, 1) == 147) ? 1u : 0u;
    __syncthreads();
    if (s_hist[0]) {
        __threadfence();
        float e = 0.f; int u = 0;
#pragma unroll
        for (int r = 0; r < 2; ++r) {
            unsigned int c = g_counts[r * 256 + tid];
            float p = (float)c * (1.0f / 131072.0f);
            if (c > 0) { e -= p * logf(p); u += 1; }
        }
#pragma unroll
        for (int o = 16; o; o >>= 1) {
            e += __shfl_xor_sync(0xffffffffu, e, o);
            u += __shfl_xor_sync(0xffffffffu, u, o);
        }
        if ((tid & 31) == 0) { s_md[tid >> 5] = e; s_mi[64 + (tid >> 5)] = u; }
        __syncthreads();
        if (tid == 0) {
            float ent = 0.f; int used = 0;
            for (int i = 0; i < 8; ++i) { ent += s_md[i]; used += s_mi[64 + i]; }
            float avg = (float)(g_dsum * (1.0 / 131072.0));
            out[OFF_SCAL + 0] = 1.25f * avg;                // loss_vq
            out[OFF_SCAL + 1] = expf(ent);                  // perplexity
            out[OFF_SCAL + 2] = (float)used;                // codes_used
            out[OFF_SCAL + 3] = (float)used / 512.0f;       // usage_ratio
            out[OFF_SCAL + 4] = avg;                        // avg_dist2
            g_done = 0;                                     // replay-safe reset
        }
    }
}

extern "C" void kernel_launch(void* const* d_in, const int* in_sizes, int n_in,
                              void* d_out, int out_size) {
    const float* z_e = (const float*)d_in[0];
    const float* emb = (const float*)d_in[1];
    float*       out = (float*)d_out;

    cudaFuncSetAttribute(vq_main, cudaFuncAttributeMaxDynamicSharedMemorySize,
                         SM_BYTES);

    vq_prep<<<2, 256>>>(emb);
    vq_main<<<148, 256, SM_BYTES>>>(z_e, emb, out);
}